// round 13
// baseline (speedup 1.0000x reference)
#include <cuda_runtime.h>
#include <cstdint>

#define B_    4096
#define D_    1024
#define M_    16384
#define KTOT  131072
#define MK    64
#define AUXK  64
#define ROWCAP 1024
#define TIECAP 2048
#define NTOT  (B_ * M_)
#define BAND  65536L          /* exact-rescue band in key space (~1.6e-2 value) */

static __device__ float g_pre[(size_t)B_ * M_];
static __device__ float g_dwT[(size_t)M_ * D_];
static __device__ float g_xc[(size_t)B_ * D_];
static __device__ float g_xhi[(size_t)B_ * D_];    // tf32-rounded xc
static __device__ float g_whi[(size_t)M_ * D_];    // tf32-rounded enc_w
static __device__ int   g_row_cnt[B_];
static __device__ int   g_row_cols[(size_t)B_ * ROWCAP];
static __device__ float g_row_vals[(size_t)B_ * ROWCAP];
static __device__ int   g_mk_cols[(size_t)B_ * MK];
static __device__ float g_mk_vals[(size_t)B_ * MK];
static __device__ unsigned g_h1[2048];
static __device__ unsigned g_h2[2048];
static __device__ unsigned g_h3[1024];
static __device__ unsigned g_selst[4];
static __device__ unsigned g_cutoff_key;
static __device__ unsigned g_tie_need;
static __device__ int g_tie_cnt;
static __device__ int g_tie_idx[TIECAP];
static __device__ unsigned char g_active[M_];
static __device__ unsigned char g_deadmask[M_];
static __device__ int g_dead_cnt;
static __device__ int g_dead_list[M_];

__device__ __forceinline__ float tf32_rna(float a) {
    uint32_t r; asm("cvt.rna.tf32.f32 %0, %1;" : "=r"(r) : "f"(a));
    return __uint_as_float(r);
}
__device__ __forceinline__ void mma_tf32(float* c, const uint32_t* a, const uint32_t* b) {
    asm volatile(
        "mma.sync.aligned.m16n8k8.row.col.f32.tf32.tf32.f32 "
        "{%0,%1,%2,%3}, {%4,%5,%6,%7}, {%8,%9}, {%0,%1,%2,%3};"
        : "+f"(c[0]), "+f"(c[1]), "+f"(c[2]), "+f"(c[3])
        : "r"(a[0]), "r"(a[1]), "r"(a[2]), "r"(a[3]), "r"(b[0]), "r"(b[1]));
}
__device__ __forceinline__ unsigned relu_key(float v) {
    return (v > 0.f) ? __float_as_uint(v) : 0u;
}
__device__ __forceinline__ unsigned ord_key(float v) {
    unsigned u = __float_as_uint(v);
    return (u & 0x80000000u) ? ~u : (u | 0x80000000u);
}

// exact reference fp32 chain (bitwise = reference GEMM, verified R1)
__device__ float exact_pre(int row, int col, const float* __restrict__ W,
                           const float* __restrict__ nb) {
    const float* xr = g_xc + (size_t)row * D_;
    const float* wr = W + (size_t)col * D_;
    float acc = 0.f;
#pragma unroll 8
    for (int k = 0; k < D_; ++k) acc = fmaf(xr[k], wr[k], acc);
    return acc + nb[col];
}

__global__ void k_init() {
    int i = blockIdx.x * blockDim.x + threadIdx.x;
    int n = blockDim.x * gridDim.x;
    for (int t = i; t < M_; t += n) g_active[t] = 0;
    for (int t = i; t < B_; t += n) g_row_cnt[t] = 0;
    for (int t = i; t < 2048; t += n) { g_h1[t] = 0; g_h2[t] = 0; }
    for (int t = i; t < 1024; t += n) g_h3[t] = 0;
    if (i == 0) { g_tie_cnt = 0; g_dead_cnt = 0; }
}

__global__ void k_center(const float* __restrict__ x, const float* __restrict__ ib) {
    int i = blockIdx.x * blockDim.x + threadIdx.x;
    int n = blockDim.x * gridDim.x;
    const float4* x4 = (const float4*)x;
    float4* o4 = (float4*)g_xc;
    float4* h4 = (float4*)g_xhi;
    for (int t = i; t < B_ * D_ / 4; t += n) {
        int d0 = (t * 4) & (D_ - 1);
        float4 xv = x4[t];
        float4 iv = *(const float4*)(ib + d0);
        float4 c = make_float4(xv.x - iv.x, xv.y - iv.y, xv.z - iv.z, xv.w - iv.w);
        o4[t] = c;
        h4[t] = make_float4(tf32_rna(c.x), tf32_rna(c.y), tf32_rna(c.z), tf32_rna(c.w));
    }
}

__global__ void k_splitw(const float* __restrict__ W) {
    int i = blockIdx.x * blockDim.x + threadIdx.x;
    int n = blockDim.x * gridDim.x;
    const float4* s4 = (const float4*)W;
    float4* h4 = (float4*)g_whi;
    for (int t = i; t < M_ * D_ / 4; t += n) {
        float4 a = s4[t];
        h4[t] = make_float4(tf32_rna(a.x), tf32_rna(a.y), tf32_rna(a.z), tf32_rna(a.w));
    }
}

__global__ void k_transpose(const float* __restrict__ dw) {
    __shared__ float t[32][33];
    int mb = blockIdx.x * 32, db = blockIdx.y * 32;
    int tx = threadIdx.x, ty = threadIdx.y;
#pragma unroll
    for (int i = 0; i < 32; i += 8)
        t[ty + i][tx] = dw[(size_t)(db + ty + i) * M_ + mb + tx];
    __syncthreads();
#pragma unroll
    for (int i = 0; i < 32; i += 8)
        g_dwT[(size_t)(mb + ty + i) * D_ + db + tx] = t[tx][ty + i];
}

// ---------------- tf32 mma.sync GEMM: pre = xhi @ whi^T + nb, fused hist1 ----------------
// C tile 128x128 per CTA; 8 warps, each 64x32; K chunks of 16; smem stride 20 (pad).
__global__ __launch_bounds__(256, 2) void k_gemm_mma(const float* __restrict__ nb) {
    __shared__ float As[128][20];
    __shared__ float Bs[128][20];
    __shared__ unsigned sh_h[2048];

    int tid = threadIdx.x;
    for (int t = tid; t < 2048; t += 256) sh_h[t] = 0;

    int n0 = blockIdx.x * 128;   // M cols
    int m0 = blockIdx.y * 128;   // batch rows
    int warp = tid >> 5, lane = tid & 31;
    int wr = warp >> 2, wc = warp & 3;   // warp row(0-1) x col(0-3)
    int lr = lane >> 2, lc = lane & 3;

    float acc[16][4];
#pragma unroll
    for (int i = 0; i < 16; i++)
#pragma unroll
        for (int j = 0; j < 4; j++) acc[i][j] = 0.f;

    // prefetch chunk 0
    int fa = tid, fb = tid + 256;           // two float4 loads each for A and B
    int rA0 = fa >> 2, qA0 = fa & 3, rA1 = fb >> 2, qA1 = fb & 3;
    float4 pa0 = *(const float4*)(g_xhi + (size_t)(m0 + rA0) * D_ + qA0 * 4);
    float4 pa1 = *(const float4*)(g_xhi + (size_t)(m0 + rA1) * D_ + qA1 * 4);
    float4 pb0 = *(const float4*)(g_whi + (size_t)(n0 + rA0) * D_ + qA0 * 4);
    float4 pb1 = *(const float4*)(g_whi + (size_t)(n0 + rA1) * D_ + qA1 * 4);

#pragma unroll 1
    for (int kt = 0; kt < 64; ++kt) {
        *(float4*)&As[rA0][qA0 * 4] = pa0;
        *(float4*)&As[rA1][qA1 * 4] = pa1;
        *(float4*)&Bs[rA0][qA0 * 4] = pb0;
        *(float4*)&Bs[rA1][qA1 * 4] = pb1;
        __syncthreads();
        if (kt < 63) {
            size_t ko = (size_t)(kt + 1) * 16;
            pa0 = *(const float4*)(g_xhi + (size_t)(m0 + rA0) * D_ + ko + qA0 * 4);
            pa1 = *(const float4*)(g_xhi + (size_t)(m0 + rA1) * D_ + ko + qA1 * 4);
            pb0 = *(const float4*)(g_whi + (size_t)(n0 + rA0) * D_ + ko + qA0 * 4);
            pb1 = *(const float4*)(g_whi + (size_t)(n0 + rA1) * D_ + ko + qA1 * 4);
        }
#pragma unroll
        for (int ks = 0; ks < 2; ++ks) {
            int k0 = ks * 8;
            uint32_t afr[4][4], bfr[4][2];
#pragma unroll
            for (int mi = 0; mi < 4; ++mi) {
                int r = 64 * wr + mi * 16 + lr;
                afr[mi][0] = __float_as_uint(As[r][k0 + lc]);
                afr[mi][1] = __float_as_uint(As[r + 8][k0 + lc]);
                afr[mi][2] = __float_as_uint(As[r][k0 + lc + 4]);
                afr[mi][3] = __float_as_uint(As[r + 8][k0 + lc + 4]);
            }
#pragma unroll
            for (int ni = 0; ni < 4; ++ni) {
                int nn = 32 * wc + ni * 8 + lr;
                bfr[ni][0] = __float_as_uint(Bs[nn][k0 + lc]);
                bfr[ni][1] = __float_as_uint(Bs[nn][k0 + lc + 4]);
            }
#pragma unroll
            for (int mi = 0; mi < 4; ++mi)
#pragma unroll
                for (int ni = 0; ni < 4; ++ni)
                    mma_tf32(acc[mi * 4 + ni], afr[mi], bfr[ni]);
        }
        __syncthreads();
    }

    // epilogue: +nb, write, fused hist1
#pragma unroll
    for (int mi = 0; mi < 4; ++mi) {
#pragma unroll
        for (int ni = 0; ni < 4; ++ni) {
            int row0 = m0 + 64 * wr + mi * 16 + lr;
            int col = n0 + 32 * wc + ni * 8 + 2 * lc;
            float b0 = nb[col], b1 = nb[col + 1];
            float* c = acc[mi * 4 + ni];
            float o0 = c[0] + b0, o1 = c[1] + b1, o2 = c[2] + b0, o3 = c[3] + b1;
            *(float2*)(g_pre + (size_t)row0 * M_ + col) = make_float2(o0, o1);
            *(float2*)(g_pre + (size_t)(row0 + 8) * M_ + col) = make_float2(o2, o3);
            atomicAdd(&sh_h[relu_key(o0) >> 21], 1u);
            atomicAdd(&sh_h[relu_key(o1) >> 21], 1u);
            atomicAdd(&sh_h[relu_key(o2) >> 21], 1u);
            atomicAdd(&sh_h[relu_key(o3) >> 21], 1u);
        }
    }
    __syncthreads();
    for (int t = tid; t < 2048; t += 256)
        if (sh_h[t]) atomicAdd(&g_h1[t], sh_h[t]);
}

// ---------------- radix machinery ----------------
__global__ void k_scan1() {
    if (threadIdx.x == 0) {
        unsigned acc = 0;
        for (int d = 2047; d >= 0; d--) {
            unsigned c = g_h1[d];
            if (acc + c >= (unsigned)KTOT) { g_selst[0] = d; g_selst[1] = KTOT - acc; break; }
            acc += c;
        }
    }
}
__global__ void k_hist2() {
    __shared__ unsigned sh[2048];
    for (int t = threadIdx.x; t < 2048; t += blockDim.x) sh[t] = 0;
    __syncthreads();
    unsigned b1 = g_selst[0];
    int stride = gridDim.x * blockDim.x;
    const float4* p4 = (const float4*)g_pre;
    for (int i = blockIdx.x * blockDim.x + threadIdx.x; i < NTOT / 4; i += stride) {
        float4 v = p4[i];
        unsigned k;
        k = relu_key(v.x); if ((k >> 21) == b1) atomicAdd(&sh[(k >> 10) & 2047], 1u);
        k = relu_key(v.y); if ((k >> 21) == b1) atomicAdd(&sh[(k >> 10) & 2047], 1u);
        k = relu_key(v.z); if ((k >> 21) == b1) atomicAdd(&sh[(k >> 10) & 2047], 1u);
        k = relu_key(v.w); if ((k >> 21) == b1) atomicAdd(&sh[(k >> 10) & 2047], 1u);
    }
    __syncthreads();
    for (int t = threadIdx.x; t < 2048; t += blockDim.x)
        if (sh[t]) atomicAdd(&g_h2[t], sh[t]);
}
__global__ void k_scan2() {
    if (threadIdx.x == 0) {
        unsigned K = g_selst[1], acc = 0;
        for (int d = 2047; d >= 0; d--) {
            unsigned c = g_h2[d];
            if (acc + c >= K) { g_selst[2] = d; g_selst[3] = K - acc; break; }
            acc += c;
        }
    }
}
__global__ void k_hist3() {
    __shared__ unsigned sh[1024];
    for (int t = threadIdx.x; t < 1024; t += blockDim.x) sh[t] = 0;
    __syncthreads();
    unsigned pre = (g_selst[0] << 11) | g_selst[2];
    int stride = gridDim.x * blockDim.x;
    const float4* p4 = (const float4*)g_pre;
    for (int i = blockIdx.x * blockDim.x + threadIdx.x; i < NTOT / 4; i += stride) {
        float4 v = p4[i];
        unsigned k;
        k = relu_key(v.x); if ((k >> 10) == pre) atomicAdd(&sh[k & 1023], 1u);
        k = relu_key(v.y); if ((k >> 10) == pre) atomicAdd(&sh[k & 1023], 1u);
        k = relu_key(v.z); if ((k >> 10) == pre) atomicAdd(&sh[k & 1023], 1u);
        k = relu_key(v.w); if ((k >> 10) == pre) atomicAdd(&sh[k & 1023], 1u);
    }
    __syncthreads();
    for (int t = threadIdx.x; t < 1024; t += blockDim.x)
        if (sh[t]) atomicAdd(&g_h3[t], sh[t]);
}
__global__ void k_scan3() {
    if (threadIdx.x == 0) {
        unsigned K = g_selst[3], acc = 0;
        for (int d = 1023; d >= 0; d--) {
            unsigned c = g_h3[d];
            if (acc + c >= K) {
                g_cutoff_key = (g_selst[0] << 21) | (g_selst[2] << 10) | (unsigned)d;
                g_tie_need = K - acc;
                break;
            }
            acc += c;
        }
    }
}

// patch exact values in +/-BAND keys around preliminary cutoff; fix g_h1
__global__ void k_gpatch(const float* __restrict__ W, const float* __restrict__ nb) {
    long ct = (long)g_cutoff_key;
    int stride = gridDim.x * blockDim.x;
    const float4* p4 = (const float4*)g_pre;
    for (int i = blockIdx.x * blockDim.x + threadIdx.x; i < NTOT / 4; i += stride) {
        float4 v = p4[i];
        const float* vp = &v.x;
#pragma unroll
        for (int c = 0; c < 4; ++c) {
            unsigned k = relu_key(vp[c]);
            if (k == 0u) continue;
            long d = (long)k - ct;
            if (d >= -BAND && d <= BAND) {
                int fi = i * 4 + c;
                float ve = exact_pre(fi >> 14, fi & (M_ - 1), W, nb);
                g_pre[fi] = ve;
                unsigned nk = relu_key(ve);
                if ((k >> 21) != (nk >> 21)) {
                    atomicAdd(&g_h1[k >> 21], 0xFFFFFFFFu);
                    atomicAdd(&g_h1[nk >> 21], 1u);
                }
            }
        }
    }
}
__global__ void k_zero23() {
    int i = blockIdx.x * blockDim.x + threadIdx.x;
    int n = blockDim.x * gridDim.x;
    for (int t = i; t < 2048; t += n) g_h2[t] = 0;
    for (int t = i; t < 1024; t += n) g_h3[t] = 0;
}

__global__ void k_select(float* __restrict__ activ) {
    unsigned cut = g_cutoff_key;
    int stride = gridDim.x * blockDim.x;
    const float4* p4 = (const float4*)g_pre;
    float4* o4 = (float4*)activ;
    for (int i = blockIdx.x * blockDim.x + threadIdx.x; i < NTOT / 4; i += stride) {
        float4 v = p4[i];
        float o[4];
        const float* vp = &v.x;
#pragma unroll
        for (int c = 0; c < 4; c++) {
            float val = vp[c];
            unsigned k = relu_key(val);
            float ov = 0.f;
            if (k > cut) {
                ov = val;
                int fi = i * 4 + c;
                int b = fi >> 14, m = fi & (M_ - 1);
                int p = atomicAdd(&g_row_cnt[b], 1);
                if (p < ROWCAP) {
                    g_row_cols[(size_t)b * ROWCAP + p] = m;
                    g_row_vals[(size_t)b * ROWCAP + p] = val;
                }
                g_active[m] = 1;
            } else if (k == cut && k != 0u) {
                int t = atomicAdd(&g_tie_cnt, 1);
                if (t < TIECAP) g_tie_idx[t] = i * 4 + c;
            }
            o[c] = ov;
        }
        o4[i] = make_float4(o[0], o[1], o[2], o[3]);
    }
}

__global__ void k_ties(float* __restrict__ activ) {
    __shared__ int tl[TIECAP];
    int n = g_tie_cnt; if (n > TIECAP) n = TIECAP;
    for (int t = threadIdx.x; t < n; t += blockDim.x) tl[t] = g_tie_idx[t];
    __syncthreads();
    for (int ph = 0; ph < n; ph++) {
        for (int i = (ph & 1) + 2 * threadIdx.x; i + 1 < n; i += 2 * blockDim.x) {
            int a = tl[i], b = tl[i + 1];
            if (a > b) { tl[i] = b; tl[i + 1] = a; }
        }
        __syncthreads();
    }
    int need = (int)g_tie_need; if (need > n) need = n;
    float cv = __uint_as_float(g_cutoff_key);
    for (int t = threadIdx.x; t < need; t += blockDim.x) {
        int fi = tl[t];
        activ[fi] = cv;
        int b = fi >> 14, m = fi & (M_ - 1);
        int p = atomicAdd(&g_row_cnt[b], 1);
        if (p < ROWCAP) {
            g_row_cols[(size_t)b * ROWCAP + p] = m;
            g_row_vals[(size_t)b * ROWCAP + p] = cv;
        }
        g_active[m] = 1;
    }
}

__global__ void k_dead(const int* __restrict__ steps32) {
    bool is64 = true;
    for (int j = 1; j < 64; j += 2)
        if (steps32[j] != 0) { is64 = false; break; }
    int i = blockIdx.x * blockDim.x + threadIdx.x;
    int n = blockDim.x * gridDim.x;
    for (int m = i; m < M_; m += n) {
        long long st = (long long)(is64 ? steps32[2 * m] : steps32[m]) + 1;
        bool dead = (!g_active[m]) && (st > 256);
        g_deadmask[m] = dead ? 1 : 0;
        if (dead) {
            int p = atomicAdd(&g_dead_cnt, 1);
            g_dead_list[p] = m;
        }
    }
}
__global__ void k_deadsort() {
    int n = g_dead_cnt; if (n > M_) n = M_;
    for (int ph = 0; ph < n; ph++) {
        for (int i = (ph & 1) + 2 * threadIdx.x; i + 1 < n; i += 2 * blockDim.x) {
            int a = g_dead_list[i], b = g_dead_list[i + 1];
            if (a > b) { g_dead_list[i] = b; g_dead_list[i + 1] = a; }
        }
        __syncthreads();
    }
}

// per-row top-64 with exact boundary rescue (+/-BAND keys around bucket)
__global__ __launch_bounds__(256) void k_multik(const float* __restrict__ W,
                                                const float* __restrict__ nb) {
    int row = blockIdx.x;
    const float* pr = g_pre + (size_t)row * M_;
    __shared__ unsigned sh[2048];
    __shared__ int sb1, sr1, sb2, snsel, sncand;
    __shared__ unsigned cekey[256];
    __shared__ float cval[256];
    __shared__ int ccol[256];
    int tid = threadIdx.x;

    for (int t = tid; t < 2048; t += 256) sh[t] = 0;
    __syncthreads();
    for (int c = tid; c < M_; c += 256)
        atomicAdd(&sh[ord_key(pr[c]) >> 21], 1u);
    __syncthreads();
    if (tid == 0) {
        unsigned acc = 0;
        for (int d = 2047; d >= 0; d--) {
            unsigned c = sh[d];
            if (acc + c >= (unsigned)MK) { sb1 = d; sr1 = MK - acc; break; }
            acc += c;
        }
    }
    __syncthreads();
    int b1 = sb1, r1 = sr1;

    for (int t = tid; t < 2048; t += 256) sh[t] = 0;
    __syncthreads();
    for (int c = tid; c < M_; c += 256) {
        unsigned k = ord_key(pr[c]);
        if ((int)(k >> 21) == b1) atomicAdd(&sh[(k >> 10) & 2047], 1u);
    }
    __syncthreads();
    if (tid == 0) {
        unsigned acc = 0;
        for (int d = 2047; d >= 0; d--) {
            unsigned c = sh[d];
            if (acc + c >= (unsigned)r1) { sb2 = d; break; }
            acc += c;
        }
        snsel = 0; sncand = 0;
    }
    __syncthreads();
    unsigned klo = ((unsigned)b1 << 21) | ((unsigned)sb2 << 10);
    unsigned clo = klo - (unsigned)BAND;
    unsigned chi = klo + 1023u + (unsigned)BAND;

    for (int c = tid; c < M_; c += 256) {
        unsigned k = ord_key(pr[c]);
        if (k > chi) {
            int p = atomicAdd(&snsel, 1);
            g_mk_cols[(size_t)row * MK + p] = c;
            g_mk_vals[(size_t)row * MK + p] = fmaxf(pr[c], 0.f);
        } else if (k >= clo) {
            int p = atomicAdd(&sncand, 1);
            if (p < 256) ccol[p] = c;
        }
    }
    __syncthreads();
    int nsel = snsel;
    int need = MK - nsel;
    int nc = sncand; if (nc > 256) nc = 256;
    for (int t = tid; t < nc; t += 256) {
        float ve = exact_pre(row, ccol[t], W, nb);
        cval[t] = ve;
        cekey[t] = ord_key(ve);
    }
    __syncthreads();
    for (int t = tid; t < nc; t += 256) {
        unsigned mk = cekey[t];
        int mc = ccol[t];
        int rank = 0;
        for (int j = 0; j < nc; j++) {
            unsigned ok = cekey[j];
            if (ok > mk || (ok == mk && ccol[j] < mc)) rank++;
        }
        if (rank < need) {
            g_mk_cols[(size_t)row * MK + nsel + rank] = mc;
            g_mk_vals[(size_t)row * MK + nsel + rank] = fmaxf(cval[t], 0.f);
        }
    }
}

// aux top-64: dead values exact; zero-fill per XLA total order with sign rescue
__global__ void k_aux(float* __restrict__ av_out, float* __restrict__ ai_out,
                      const float* __restrict__ W, const float* __restrict__ nb) {
    int row = blockIdx.x * blockDim.x + threadIdx.x;
    if (row >= B_) return;
    const float* pr = g_pre + (size_t)row * M_;
    float pv[AUXK];
    int pidx[AUXK];
    int np = 0;
    int nd = g_dead_cnt; if (nd > M_) nd = M_;
    for (int t = 0; t < nd; t++) {
        int m = g_dead_list[t];
        float v = exact_pre(row, m, W, nb);    // dead values: always exact
        if (v > 0.f) {
            if (np == AUXK && v <= pv[AUXK - 1]) continue;
            int ins = (np < AUXK) ? np : AUXK - 1;
            while (ins > 0 && pv[ins - 1] < v) {
                pv[ins] = pv[ins - 1]; pidx[ins] = pidx[ins - 1]; ins--;
            }
            pv[ins] = v; pidx[ins] = m;
            if (np < AUXK) np++;
        }
    }
    float* av = av_out + (size_t)row * AUXK;
    float* ai = ai_out + (size_t)row * AUXK;
    int s = 0;
    for (; s < np; s++) { av[s] = pv[s]; ai[s] = (float)pidx[s]; }
    int j = 0;
    while (s < AUXK && j < M_) {
        float v = pr[j];
        unsigned bits = __float_as_uint(v);
        if (fabsf(v) < 2e-2f) bits = __float_as_uint(exact_pre(row, j, W, nb));
        bool pz;
        if (g_deadmask[j]) pz = (bits == 0u);
        else               pz = ((bits & 0x80000000u) == 0u);
        if (pz) { av[s] = 0.f; ai[s] = (float)j; s++; }
        j++;
    }
    j = 0;
    while (s < AUXK && j < M_) {
        float v = pr[j];
        unsigned bits = __float_as_uint(v);
        if (fabsf(v) < 2e-2f) bits = __float_as_uint(exact_pre(row, j, W, nb));
        bool mz;
        if (g_deadmask[j]) mz = (bits == 0x80000000u);
        else               mz = ((bits & 0x80000000u) != 0u);
        if (mz) { av[s] = 0.f; ai[s] = (float)j; s++; }
        j++;
    }
    while (s < AUXK) { av[s] = 0.f; ai[s] = 0.f; s++; }
}

__global__ void k_recon(float* __restrict__ out, const float* __restrict__ ib) {
    int row = blockIdx.x;
    int d0 = threadIdx.x * 4;
    float4 acc = *(const float4*)(ib + d0);
    int n = g_row_cnt[row]; if (n > ROWCAP) n = ROWCAP;
    const int* cols = g_row_cols + (size_t)row * ROWCAP;
    const float* vals = g_row_vals + (size_t)row * ROWCAP;
    for (int i = 0; i < n; i++) {
        int m = cols[i];
        float v = vals[i];
        float4 w = *(const float4*)(g_dwT + (size_t)m * D_ + d0);
        acc.x = fmaf(v, w.x, acc.x);
        acc.y = fmaf(v, w.y, acc.y);
        acc.z = fmaf(v, w.z, acc.z);
        acc.w = fmaf(v, w.w, acc.w);
    }
    *(float4*)(out + (size_t)row * D_ + d0) = acc;
}

__global__ void k_mkrecon(float* __restrict__ out, const float* __restrict__ ib) {
    int row = blockIdx.x;
    int d0 = threadIdx.x * 4;
    float4 acc = *(const float4*)(ib + d0);
    const int* cols = g_mk_cols + (size_t)row * MK;
    const float* vals = g_mk_vals + (size_t)row * MK;
#pragma unroll 4
    for (int i = 0; i < MK; i++) {
        int m = cols[i];
        float v = vals[i];
        float4 w = *(const float4*)(g_dwT + (size_t)m * D_ + d0);
        acc.x = fmaf(v, w.x, acc.x);
        acc.y = fmaf(v, w.y, acc.y);
        acc.z = fmaf(v, w.z, acc.z);
        acc.w = fmaf(v, w.w, acc.w);
    }
    *(float4*)(out + (size_t)row * D_ + d0) = acc;
}

extern "C" void kernel_launch(void* const* d_in, const int* in_sizes, int n_in,
                              void* d_out, int out_size) {
    const float* x     = (const float*)d_in[0];
    const float* enc_w = (const float*)d_in[1];
    const float* dec_w = (const float*)d_in[2];
    const float* ib    = (const float*)d_in[3];
    const float* nb    = (const float*)d_in[4];
    const int*   steps = (const int*)d_in[5];

    float* out = (float*)d_out;
    float* o_recon   = out;
    float* o_activ   = o_recon + (size_t)B_ * D_;
    float* o_mkrecon = o_activ + (size_t)B_ * M_;
    float* o_auxv    = o_mkrecon + (size_t)B_ * D_;
    float* o_auxi    = o_auxv + (size_t)B_ * AUXK;

    k_init<<<64, 256>>>();
    k_center<<<512, 256>>>(x, ib);
    k_splitw<<<2048, 256>>>(enc_w);
    k_transpose<<<dim3(M_ / 32, D_ / 32), dim3(32, 8)>>>(dec_w);
    k_gemm_mma<<<dim3(M_ / 128, B_ / 128), 256>>>(nb);
    // preliminary cutoff from tensor data
    k_scan1<<<1, 32>>>();
    k_hist2<<<2048, 256>>>();
    k_scan2<<<1, 32>>>();
    k_hist3<<<2048, 256>>>();
    k_scan3<<<1, 32>>>();
    // exact patch of boundary band, then re-scan on patched data
    k_gpatch<<<2048, 256>>>(enc_w, nb);
    k_zero23<<<64, 256>>>();
    k_scan1<<<1, 32>>>();
    k_hist2<<<2048, 256>>>();
    k_scan2<<<1, 32>>>();
    k_hist3<<<2048, 256>>>();
    k_scan3<<<1, 32>>>();
    k_select<<<2048, 256>>>(o_activ);
    k_ties<<<1, 256>>>(o_activ);
    k_dead<<<64, 256>>>(steps);
    k_deadsort<<<1, 256>>>();
    k_multik<<<B_, 256>>>(enc_w, nb);
    k_aux<<<(B_ + 127) / 128, 128>>>(o_auxv, o_auxi, enc_w, nb);
    k_recon<<<B_, 256>>>(o_recon, ib);
    k_mkrecon<<<B_, 256>>>(o_mkrecon, ib);
}

// round 15
// speedup vs baseline: 1.0158x; 1.0158x over previous
#include <cuda_runtime.h>
#include <cstdint>

#define B_    4096
#define D_    1024
#define M_    16384
#define KTOT  131072
#define MK    64
#define AUXK  64
#define ROWCAP 1024
#define TIECAP 2048
#define NTOT  (B_ * M_)
#define BAND  65536L          /* exact-rescue band in key space (~1.6e-2 value) */

static __device__ float g_pre[(size_t)B_ * M_];
static __device__ float g_dwT[(size_t)M_ * D_];
static __device__ float g_xc[(size_t)B_ * D_];
static __device__ float g_xhi[(size_t)B_ * D_];    // tf32-rounded xc
static __device__ float g_whi[(size_t)M_ * D_];    // tf32-rounded enc_w
static __device__ int   g_row_cnt[B_];
static __device__ int   g_row_cols[(size_t)B_ * ROWCAP];
static __device__ float g_row_vals[(size_t)B_ * ROWCAP];
static __device__ int   g_mk_cols[(size_t)B_ * MK];
static __device__ float g_mk_vals[(size_t)B_ * MK];
static __device__ unsigned g_h1[2048];
static __device__ unsigned g_h2[2048];
static __device__ unsigned g_h3[1024];
static __device__ unsigned g_selst[4];
static __device__ unsigned g_cutoff_key;
static __device__ unsigned g_tie_need;
static __device__ int g_tie_cnt;
static __device__ int g_tie_idx[TIECAP];
static __device__ unsigned char g_active[M_];
static __device__ unsigned char g_deadmask[M_];
static __device__ int g_dead_cnt;
static __device__ int g_dead_list[M_];

__device__ __forceinline__ float tf32_rna(float a) {
    uint32_t r; asm("cvt.rna.tf32.f32 %0, %1;" : "=r"(r) : "f"(a));
    return __uint_as_float(r);
}
__device__ __forceinline__ void mma_tf32(float* c, const uint32_t* a, const uint32_t* b) {
    asm volatile(
        "mma.sync.aligned.m16n8k8.row.col.f32.tf32.tf32.f32 "
        "{%0,%1,%2,%3}, {%4,%5,%6,%7}, {%8,%9}, {%0,%1,%2,%3};"
        : "+f"(c[0]), "+f"(c[1]), "+f"(c[2]), "+f"(c[3])
        : "r"(a[0]), "r"(a[1]), "r"(a[2]), "r"(a[3]), "r"(b[0]), "r"(b[1]));
}
__device__ __forceinline__ void cp16(uint32_t sdst, const void* gsrc) {
    asm volatile("cp.async.cg.shared.global [%0], [%1], 16;" :: "r"(sdst), "l"(gsrc));
}
#define CP_COMMIT() asm volatile("cp.async.commit_group;" ::: "memory")
#define CP_WAIT(n)  asm volatile("cp.async.wait_group %0;" :: "n"(n) : "memory")

__device__ __forceinline__ unsigned relu_key(float v) {
    return (v > 0.f) ? __float_as_uint(v) : 0u;
}
__device__ __forceinline__ unsigned ord_key(float v) {
    unsigned u = __float_as_uint(v);
    return (u & 0x80000000u) ? ~u : (u | 0x80000000u);
}

// exact reference fp32 chain (bitwise = reference GEMM, verified R1)
__device__ float exact_pre(int row, int col, const float* __restrict__ W,
                           const float* __restrict__ nb) {
    const float* xr = g_xc + (size_t)row * D_;
    const float* wr = W + (size_t)col * D_;
    float acc = 0.f;
#pragma unroll 8
    for (int k = 0; k < D_; ++k) acc = fmaf(xr[k], wr[k], acc);
    return acc + nb[col];
}

__global__ void k_init() {
    int i = blockIdx.x * blockDim.x + threadIdx.x;
    int n = blockDim.x * gridDim.x;
    for (int t = i; t < M_; t += n) g_active[t] = 0;
    for (int t = i; t < B_; t += n) g_row_cnt[t] = 0;
    for (int t = i; t < 2048; t += n) { g_h1[t] = 0; g_h2[t] = 0; }
    for (int t = i; t < 1024; t += n) g_h3[t] = 0;
    if (i == 0) { g_tie_cnt = 0; g_dead_cnt = 0; }
}

// fused: center x (xc, xhi) + tf32-round W (whi)
__global__ void k_prep(const float* __restrict__ x, const float* __restrict__ ib,
                       const float* __restrict__ W) {
    int i = blockIdx.x * blockDim.x + threadIdx.x;
    int n = blockDim.x * gridDim.x;
    const float4* x4 = (const float4*)x;
    float4* o4 = (float4*)g_xc;
    float4* h4 = (float4*)g_xhi;
    for (int t = i; t < B_ * D_ / 4; t += n) {
        int d0 = (t * 4) & (D_ - 1);
        float4 xv = x4[t];
        float4 iv = *(const float4*)(ib + d0);
        float4 c = make_float4(xv.x - iv.x, xv.y - iv.y, xv.z - iv.z, xv.w - iv.w);
        o4[t] = c;
        h4[t] = make_float4(tf32_rna(c.x), tf32_rna(c.y), tf32_rna(c.z), tf32_rna(c.w));
    }
    const float4* s4 = (const float4*)W;
    float4* wh4 = (float4*)g_whi;
    for (int t = i; t < M_ * D_ / 4; t += n) {
        float4 a = s4[t];
        wh4[t] = make_float4(tf32_rna(a.x), tf32_rna(a.y), tf32_rna(a.z), tf32_rna(a.w));
    }
}

__global__ void k_transpose(const float* __restrict__ dw) {
    __shared__ float t[32][33];
    int mb = blockIdx.x * 32, db = blockIdx.y * 32;
    int tx = threadIdx.x, ty = threadIdx.y;
#pragma unroll
    for (int i = 0; i < 32; i += 8)
        t[ty + i][tx] = dw[(size_t)(db + ty + i) * M_ + mb + tx];
    __syncthreads();
#pragma unroll
    for (int i = 0; i < 32; i += 8)
        g_dwT[(size_t)(mb + ty + i) * D_ + db + tx] = t[tx][ty + i];
}

// ---------------- tf32 mma.sync GEMM: pre = xhi @ whi^T + nb, fused hist1 ----------------
// C tile 128x128 per CTA; 8 warps, each 64x32; K chunks of 16; smem stride 20 (pad);
// cp.async double buffer; no reg-count cap (avoid accumulator spill).
__global__ __launch_bounds__(256) void k_gemm_mma(const float* __restrict__ nb) {
    __shared__ __align__(16) float As[2][128][20];
    __shared__ __align__(16) float Bs[2][128][20];
    __shared__ unsigned sh_h[2048];

    int tid = threadIdx.x;
    for (int t = tid; t < 2048; t += 256) sh_h[t] = 0;

    int n0 = blockIdx.x * 128;   // M cols
    int m0 = blockIdx.y * 128;   // batch rows
    int warp = tid >> 5, lane = tid & 31;
    int wr = warp >> 2, wc = warp & 3;   // warp row(0-1) x col(0-3)
    int lr = lane >> 2, lc = lane & 3;

    // per-thread load coords: two rows, 16B each, for A and B
    int rA0 = tid >> 2, qA0 = (tid & 3) * 4;
    int rA1 = (tid + 256) >> 2, qA1 = ((tid + 256) & 3) * 4;
    const float* gA0 = g_xhi + (size_t)(m0 + rA0) * D_ + qA0;
    const float* gA1 = g_xhi + (size_t)(m0 + rA1) * D_ + qA1;
    const float* gB0 = g_whi + (size_t)(n0 + rA0) * D_ + qA0;
    const float* gB1 = g_whi + (size_t)(n0 + rA1) * D_ + qA1;
    uint32_t sA0[2], sA1[2], sB0[2], sB1[2];
#pragma unroll
    for (int b = 0; b < 2; ++b) {
        sA0[b] = (uint32_t)__cvta_generic_to_shared(&As[b][rA0][qA0]);
        sA1[b] = (uint32_t)__cvta_generic_to_shared(&As[b][rA1][qA1]);
        sB0[b] = (uint32_t)__cvta_generic_to_shared(&Bs[b][rA0][qA0]);
        sB1[b] = (uint32_t)__cvta_generic_to_shared(&Bs[b][rA1][qA1]);
    }

    float acc[16][4];
#pragma unroll
    for (int i = 0; i < 16; i++)
#pragma unroll
        for (int j = 0; j < 4; j++) acc[i][j] = 0.f;

    // prologue: stage 0
    cp16(sA0[0], gA0); cp16(sA1[0], gA1);
    cp16(sB0[0], gB0); cp16(sB1[0], gB1);
    CP_COMMIT();

    int buf = 0;
#pragma unroll 1
    for (int kt = 0; kt < 64; ++kt) {
        if (kt < 63) {
            int ko = (kt + 1) * 16;
            int nb_ = buf ^ 1;
            cp16(sA0[nb_], gA0 + ko); cp16(sA1[nb_], gA1 + ko);
            cp16(sB0[nb_], gB0 + ko); cp16(sB1[nb_], gB1 + ko);
            CP_COMMIT();
            CP_WAIT(1);
        } else {
            CP_WAIT(0);
        }
        __syncthreads();
#pragma unroll
        for (int ks = 0; ks < 2; ++ks) {
            int k0 = ks * 8;
            uint32_t afr[4][4], bfr[4][2];
#pragma unroll
            for (int mi = 0; mi < 4; ++mi) {
                int r = 64 * wr + mi * 16 + lr;
                afr[mi][0] = __float_as_uint(As[buf][r][k0 + lc]);
                afr[mi][1] = __float_as_uint(As[buf][r + 8][k0 + lc]);
                afr[mi][2] = __float_as_uint(As[buf][r][k0 + lc + 4]);
                afr[mi][3] = __float_as_uint(As[buf][r + 8][k0 + lc + 4]);
            }
#pragma unroll
            for (int ni = 0; ni < 4; ++ni) {
                int nn = 32 * wc + ni * 8 + lr;
                bfr[ni][0] = __float_as_uint(Bs[buf][nn][k0 + lc]);
                bfr[ni][1] = __float_as_uint(Bs[buf][nn][k0 + lc + 4]);
            }
#pragma unroll
            for (int mi = 0; mi < 4; ++mi)
#pragma unroll
                for (int ni = 0; ni < 4; ++ni)
                    mma_tf32(acc[mi * 4 + ni], afr[mi], bfr[ni]);
        }
        __syncthreads();
        buf ^= 1;
    }

    // epilogue: +nb, write, fused hist1
#pragma unroll
    for (int mi = 0; mi < 4; ++mi) {
#pragma unroll
        for (int ni = 0; ni < 4; ++ni) {
            int row0 = m0 + 64 * wr + mi * 16 + lr;
            int col = n0 + 32 * wc + ni * 8 + 2 * lc;
            float b0 = nb[col], b1 = nb[col + 1];
            float* c = acc[mi * 4 + ni];
            float o0 = c[0] + b0, o1 = c[1] + b1, o2 = c[2] + b0, o3 = c[3] + b1;
            *(float2*)(g_pre + (size_t)row0 * M_ + col) = make_float2(o0, o1);
            *(float2*)(g_pre + (size_t)(row0 + 8) * M_ + col) = make_float2(o2, o3);
            atomicAdd(&sh_h[relu_key(o0) >> 21], 1u);
            atomicAdd(&sh_h[relu_key(o1) >> 21], 1u);
            atomicAdd(&sh_h[relu_key(o2) >> 21], 1u);
            atomicAdd(&sh_h[relu_key(o3) >> 21], 1u);
        }
    }
    __syncthreads();
    for (int t = tid; t < 2048; t += 256)
        if (sh_h[t]) atomicAdd(&g_h1[t], sh_h[t]);
}

// ---------------- radix machinery ----------------
__global__ void k_scan1() {
    if (threadIdx.x == 0) {
        unsigned acc = 0;
        for (int d = 2047; d >= 0; d--) {
            unsigned c = g_h1[d];
            if (acc + c >= (unsigned)KTOT) { g_selst[0] = d; g_selst[1] = KTOT - acc; break; }
            acc += c;
        }
    }
}
__global__ void k_hist2() {
    __shared__ unsigned sh[2048];
    for (int t = threadIdx.x; t < 2048; t += blockDim.x) sh[t] = 0;
    __syncthreads();
    unsigned b1 = g_selst[0];
    int stride = gridDim.x * blockDim.x;
    const float4* p4 = (const float4*)g_pre;
    for (int i = blockIdx.x * blockDim.x + threadIdx.x; i < NTOT / 4; i += stride) {
        float4 v = p4[i];
        unsigned k;
        k = relu_key(v.x); if ((k >> 21) == b1) atomicAdd(&sh[(k >> 10) & 2047], 1u);
        k = relu_key(v.y); if ((k >> 21) == b1) atomicAdd(&sh[(k >> 10) & 2047], 1u);
        k = relu_key(v.z); if ((k >> 21) == b1) atomicAdd(&sh[(k >> 10) & 2047], 1u);
        k = relu_key(v.w); if ((k >> 21) == b1) atomicAdd(&sh[(k >> 10) & 2047], 1u);
    }
    __syncthreads();
    for (int t = threadIdx.x; t < 2048; t += blockDim.x)
        if (sh[t]) atomicAdd(&g_h2[t], sh[t]);
}
__global__ void k_scan2() {
    if (threadIdx.x == 0) {
        unsigned K = g_selst[1], acc = 0;
        for (int d = 2047; d >= 0; d--) {
            unsigned c = g_h2[d];
            if (acc + c >= K) { g_selst[2] = d; g_selst[3] = K - acc; break; }
            acc += c;
        }
    }
}
__global__ void k_hist3() {
    __shared__ unsigned sh[1024];
    for (int t = threadIdx.x; t < 1024; t += blockDim.x) sh[t] = 0;
    __syncthreads();
    unsigned pre = (g_selst[0] << 11) | g_selst[2];
    int stride = gridDim.x * blockDim.x;
    const float4* p4 = (const float4*)g_pre;
    for (int i = blockIdx.x * blockDim.x + threadIdx.x; i < NTOT / 4; i += stride) {
        float4 v = p4[i];
        unsigned k;
        k = relu_key(v.x); if ((k >> 10) == pre) atomicAdd(&sh[k & 1023], 1u);
        k = relu_key(v.y); if ((k >> 10) == pre) atomicAdd(&sh[k & 1023], 1u);
        k = relu_key(v.z); if ((k >> 10) == pre) atomicAdd(&sh[k & 1023], 1u);
        k = relu_key(v.w); if ((k >> 10) == pre) atomicAdd(&sh[k & 1023], 1u);
    }
    __syncthreads();
    for (int t = threadIdx.x; t < 1024; t += blockDim.x)
        if (sh[t]) atomicAdd(&g_h3[t], sh[t]);
}
__global__ void k_scan3() {
    if (threadIdx.x == 0) {
        unsigned K = g_selst[3], acc = 0;
        for (int d = 1023; d >= 0; d--) {
            unsigned c = g_h3[d];
            if (acc + c >= K) {
                g_cutoff_key = (g_selst[0] << 21) | (g_selst[2] << 10) | (unsigned)d;
                g_tie_need = K - acc;
                break;
            }
            acc += c;
        }
    }
}

// patch exact values in +/-BAND keys around preliminary cutoff; fix g_h1
__global__ void k_gpatch(const float* __restrict__ W, const float* __restrict__ nb) {
    long ct = (long)g_cutoff_key;
    int stride = gridDim.x * blockDim.x;
    const float4* p4 = (const float4*)g_pre;
    for (int i = blockIdx.x * blockDim.x + threadIdx.x; i < NTOT / 4; i += stride) {
        float4 v = p4[i];
        const float* vp = &v.x;
#pragma unroll
        for (int c = 0; c < 4; ++c) {
            unsigned k = relu_key(vp[c]);
            if (k == 0u) continue;
            long d = (long)k - ct;
            if (d >= -BAND && d <= BAND) {
                int fi = i * 4 + c;
                float ve = exact_pre(fi >> 14, fi & (M_ - 1), W, nb);
                g_pre[fi] = ve;
                unsigned nk = relu_key(ve);
                if ((k >> 21) != (nk >> 21)) {
                    atomicAdd(&g_h1[k >> 21], 0xFFFFFFFFu);
                    atomicAdd(&g_h1[nk >> 21], 1u);
                }
            }
        }
    }
}
__global__ void k_zero23() {
    int i = blockIdx.x * blockDim.x + threadIdx.x;
    int n = blockDim.x * gridDim.x;
    for (int t = i; t < 2048; t += n) g_h2[t] = 0;
    for (int t = i; t < 1024; t += n) g_h3[t] = 0;
}

__global__ void k_select(float* __restrict__ activ) {
    unsigned cut = g_cutoff_key;
    int stride = gridDim.x * blockDim.x;
    const float4* p4 = (const float4*)g_pre;
    float4* o4 = (float4*)activ;
    for (int i = blockIdx.x * blockDim.x + threadIdx.x; i < NTOT / 4; i += stride) {
        float4 v = p4[i];
        float o[4];
        const float* vp = &v.x;
#pragma unroll
        for (int c = 0; c < 4; c++) {
            float val = vp[c];
            unsigned k = relu_key(val);
            float ov = 0.f;
            if (k > cut) {
                ov = val;
                int fi = i * 4 + c;
                int b = fi >> 14, m = fi & (M_ - 1);
                int p = atomicAdd(&g_row_cnt[b], 1);
                if (p < ROWCAP) {
                    g_row_cols[(size_t)b * ROWCAP + p] = m;
                    g_row_vals[(size_t)b * ROWCAP + p] = val;
                }
                g_active[m] = 1;
            } else if (k == cut && k != 0u) {
                int t = atomicAdd(&g_tie_cnt, 1);
                if (t < TIECAP) g_tie_idx[t] = i * 4 + c;
            }
            o[c] = ov;
        }
        o4[i] = make_float4(o[0], o[1], o[2], o[3]);
    }
}

__global__ void k_ties(float* __restrict__ activ) {
    __shared__ int tl[TIECAP];
    int n = g_tie_cnt; if (n > TIECAP) n = TIECAP;
    for (int t = threadIdx.x; t < n; t += blockDim.x) tl[t] = g_tie_idx[t];
    __syncthreads();
    for (int ph = 0; ph < n; ph++) {
        for (int i = (ph & 1) + 2 * threadIdx.x; i + 1 < n; i += 2 * blockDim.x) {
            int a = tl[i], b = tl[i + 1];
            if (a > b) { tl[i] = b; tl[i + 1] = a; }
        }
        __syncthreads();
    }
    int need = (int)g_tie_need; if (need > n) need = n;
    float cv = __uint_as_float(g_cutoff_key);
    for (int t = threadIdx.x; t < need; t += blockDim.x) {
        int fi = tl[t];
        activ[fi] = cv;
        int b = fi >> 14, m = fi & (M_ - 1);
        int p = atomicAdd(&g_row_cnt[b], 1);
        if (p < ROWCAP) {
            g_row_cols[(size_t)b * ROWCAP + p] = m;
            g_row_vals[(size_t)b * ROWCAP + p] = cv;
        }
        g_active[m] = 1;
    }
}

__global__ void k_dead(const int* __restrict__ steps32) {
    bool is64 = true;
    for (int j = 1; j < 64; j += 2)
        if (steps32[j] != 0) { is64 = false; break; }
    int i = blockIdx.x * blockDim.x + threadIdx.x;
    int n = blockDim.x * gridDim.x;
    for (int m = i; m < M_; m += n) {
        long long st = (long long)(is64 ? steps32[2 * m] : steps32[m]) + 1;
        bool dead = (!g_active[m]) && (st > 256);
        g_deadmask[m] = dead ? 1 : 0;
        if (dead) {
            int p = atomicAdd(&g_dead_cnt, 1);
            g_dead_list[p] = m;
        }
    }
}
__global__ void k_deadsort() {
    int n = g_dead_cnt; if (n > M_) n = M_;
    for (int ph = 0; ph < n; ph++) {
        for (int i = (ph & 1) + 2 * threadIdx.x; i + 1 < n; i += 2 * blockDim.x) {
            int a = g_dead_list[i], b = g_dead_list[i + 1];
            if (a > b) { g_dead_list[i] = b; g_dead_list[i + 1] = a; }
        }
        __syncthreads();
    }
}

// per-row top-64 with exact boundary rescue (+/-BAND keys around bucket)
__global__ __launch_bounds__(256) void k_multik(const float* __restrict__ W,
                                                const float* __restrict__ nb) {
    int row = blockIdx.x;
    const float* pr = g_pre + (size_t)row * M_;
    __shared__ unsigned sh[2048];
    __shared__ int sb1, sr1, sb2, snsel, sncand;
    __shared__ unsigned cekey[256];
    __shared__ float cval[256];
    __shared__ int ccol[256];
    int tid = threadIdx.x;

    for (int t = tid; t < 2048; t += 256) sh[t] = 0;
    __syncthreads();
    for (int c = tid; c < M_; c += 256)
        atomicAdd(&sh[ord_key(pr[c]) >> 21], 1u);
    __syncthreads();
    if (tid == 0) {
        unsigned acc = 0;
        for (int d = 2047; d >= 0; d--) {
            unsigned c = sh[d];
            if (acc + c >= (unsigned)MK) { sb1 = d; sr1 = MK - acc; break; }
            acc += c;
        }
    }
    __syncthreads();
    int b1 = sb1, r1 = sr1;

    for (int t = tid; t < 2048; t += 256) sh[t] = 0;
    __syncthreads();
    for (int c = tid; c < M_; c += 256) {
        unsigned k = ord_key(pr[c]);
        if ((int)(k >> 21) == b1) atomicAdd(&sh[(k >> 10) & 2047], 1u);
    }
    __syncthreads();
    if (tid == 0) {
        unsigned acc = 0;
        for (int d = 2047; d >= 0; d--) {
            unsigned c = sh[d];
            if (acc + c >= (unsigned)r1) { sb2 = d; break; }
            acc += c;
        }
        snsel = 0; sncand = 0;
    }
    __syncthreads();
    unsigned klo = ((unsigned)b1 << 21) | ((unsigned)sb2 << 10);
    unsigned clo = klo - (unsigned)BAND;
    unsigned chi = klo + 1023u + (unsigned)BAND;

    for (int c = tid; c < M_; c += 256) {
        unsigned k = ord_key(pr[c]);
        if (k > chi) {
            int p = atomicAdd(&snsel, 1);
            g_mk_cols[(size_t)row * MK + p] = c;
            g_mk_vals[(size_t)row * MK + p] = fmaxf(pr[c], 0.f);
        } else if (k >= clo) {
            int p = atomicAdd(&sncand, 1);
            if (p < 256) ccol[p] = c;
        }
    }
    __syncthreads();
    int nsel = snsel;
    int need = MK - nsel;
    int nc = sncand; if (nc > 256) nc = 256;
    for (int t = tid; t < nc; t += 256) {
        float ve = exact_pre(row, ccol[t], W, nb);
        cval[t] = ve;
        cekey[t] = ord_key(ve);
    }
    __syncthreads();
    for (int t = tid; t < nc; t += 256) {
        unsigned mk = cekey[t];
        int mc = ccol[t];
        int rank = 0;
        for (int j = 0; j < nc; j++) {
            unsigned ok = cekey[j];
            if (ok > mk || (ok == mk && ccol[j] < mc)) rank++;
        }
        if (rank < need) {
            g_mk_cols[(size_t)row * MK + nsel + rank] = mc;
            g_mk_vals[(size_t)row * MK + nsel + rank] = fmaxf(cval[t], 0.f);
        }
    }
}

// aux top-64: dead values exact; zero-fill per XLA total order with sign rescue
__global__ void k_aux(float* __restrict__ av_out, float* __restrict__ ai_out,
                      const float* __restrict__ W, const float* __restrict__ nb) {
    int row = blockIdx.x * blockDim.x + threadIdx.x;
    if (row >= B_) return;
    const float* pr = g_pre + (size_t)row * M_;
    float pv[AUXK];
    int pidx[AUXK];
    int np = 0;
    int nd = g_dead_cnt; if (nd > M_) nd = M_;
    for (int t = 0; t < nd; t++) {
        int m = g_dead_list[t];
        float v = exact_pre(row, m, W, nb);    // dead values: always exact
        if (v > 0.f) {
            if (np == AUXK && v <= pv[AUXK - 1]) continue;
            int ins = (np < AUXK) ? np : AUXK - 1;
            while (ins > 0 && pv[ins - 1] < v) {
                pv[ins] = pv[ins - 1]; pidx[ins] = pidx[ins - 1]; ins--;
            }
            pv[ins] = v; pidx[ins] = m;
            if (np < AUXK) np++;
        }
    }
    float* av = av_out + (size_t)row * AUXK;
    float* ai = ai_out + (size_t)row * AUXK;
    int s = 0;
    for (; s < np; s++) { av[s] = pv[s]; ai[s] = (float)pidx[s]; }
    int j = 0;
    while (s < AUXK && j < M_) {
        float v = pr[j];
        unsigned bits = __float_as_uint(v);
        if (fabsf(v) < 2e-2f) bits = __float_as_uint(exact_pre(row, j, W, nb));
        bool pz;
        if (g_deadmask[j]) pz = (bits == 0u);
        else               pz = ((bits & 0x80000000u) == 0u);
        if (pz) { av[s] = 0.f; ai[s] = (float)j; s++; }
        j++;
    }
    j = 0;
    while (s < AUXK && j < M_) {
        float v = pr[j];
        unsigned bits = __float_as_uint(v);
        if (fabsf(v) < 2e-2f) bits = __float_as_uint(exact_pre(row, j, W, nb));
        bool mz;
        if (g_deadmask[j]) mz = (bits == 0x80000000u);
        else               mz = ((bits & 0x80000000u) != 0u);
        if (mz) { av[s] = 0.f; ai[s] = (float)j; s++; }
        j++;
    }
    while (s < AUXK) { av[s] = 0.f; ai[s] = 0.f; s++; }
}

__global__ void k_recon(float* __restrict__ out, const float* __restrict__ ib) {
    int row = blockIdx.x;
    int d0 = threadIdx.x * 4;
    float4 acc = *(const float4*)(ib + d0);
    int n = g_row_cnt[row]; if (n > ROWCAP) n = ROWCAP;
    const int* cols = g_row_cols + (size_t)row * ROWCAP;
    const float* vals = g_row_vals + (size_t)row * ROWCAP;
    for (int i = 0; i < n; i++) {
        int m = cols[i];
        float v = vals[i];
        float4 w = *(const float4*)(g_dwT + (size_t)m * D_ + d0);
        acc.x = fmaf(v, w.x, acc.x);
        acc.y = fmaf(v, w.y, acc.y);
        acc.z = fmaf(v, w.z, acc.z);
        acc.w = fmaf(v, w.w, acc.w);
    }
    *(float4*)(out + (size_t)row * D_ + d0) = acc;
}

__global__ void k_mkrecon(float* __restrict__ out, const float* __restrict__ ib) {
    int row = blockIdx.x;
    int d0 = threadIdx.x * 4;
    float4 acc = *(const float4*)(ib + d0);
    const int* cols = g_mk_cols + (size_t)row * MK;
    const float* vals = g_mk_vals + (size_t)row * MK;
#pragma unroll 4
    for (int i = 0; i < MK; i++) {
        int m = cols[i];
        float v = vals[i];
        float4 w = *(const float4*)(g_dwT + (size_t)m * D_ + d0);
        acc.x = fmaf(v, w.x, acc.x);
        acc.y = fmaf(v, w.y, acc.y);
        acc.z = fmaf(v, w.z, acc.z);
        acc.w = fmaf(v, w.w, acc.w);
    }
    *(float4*)(out + (size_t)row * D_ + d0) = acc;
}

extern "C" void kernel_launch(void* const* d_in, const int* in_sizes, int n_in,
                              void* d_out, int out_size) {
    const float* x     = (const float*)d_in[0];
    const float* enc_w = (const float*)d_in[1];
    const float* dec_w = (const float*)d_in[2];
    const float* ib    = (const float*)d_in[3];
    const float* nb    = (const float*)d_in[4];
    const int*   steps = (const int*)d_in[5];

    float* out = (float*)d_out;
    float* o_recon   = out;
    float* o_activ   = o_recon + (size_t)B_ * D_;
    float* o_mkrecon = o_activ + (size_t)B_ * M_;
    float* o_auxv    = o_mkrecon + (size_t)B_ * D_;
    float* o_auxi    = o_auxv + (size_t)B_ * AUXK;

    k_init<<<64, 256>>>();                                   // launch 0
    k_prep<<<1024, 256>>>(x, ib, enc_w);                     // launch 1 (center + splitw fused)
    k_transpose<<<dim3(M_ / 32, D_ / 32), dim3(32, 8)>>>(dec_w);  // launch 2
    k_gemm_mma<<<dim3(M_ / 128, B_ / 128), 256>>>(nb);       // launch 3 -> ncu capture slot
    // preliminary cutoff from tensor data
    k_scan1<<<1, 32>>>();
    k_hist2<<<2048, 256>>>();
    k_scan2<<<1, 32>>>();
    k_hist3<<<2048, 256>>>();
    k_scan3<<<1, 32>>>();
    // exact patch of boundary band, then re-scan on patched data
    k_gpatch<<<2048, 256>>>(enc_w, nb);
    k_zero23<<<64, 256>>>();
    k_scan1<<<1, 32>>>();
    k_hist2<<<2048, 256>>>();
    k_scan2<<<1, 32>>>();
    k_hist3<<<2048, 256>>>();
    k_scan3<<<1, 32>>>();
    k_select<<<2048, 256>>>(o_activ);
    k_ties<<<1, 256>>>(o_activ);
    k_dead<<<64, 256>>>(steps);
    k_deadsort<<<1, 256>>>();
    k_multik<<<B_, 256>>>(enc_w, nb);
    k_aux<<<(B_ + 127) / 128, 128>>>(o_auxv, o_auxi, enc_w, nb);
    k_recon<<<B_, 256>>>(o_recon, ib);
    k_mkrecon<<<B_, 256>>>(o_mkrecon, ib);
}